// round 3
// baseline (speedup 1.0000x reference)
#include <cuda_runtime.h>
#include <cuda_bf16.h>
#include <math_constants.h>

#define NNODES 50000
#define NEDGES 800000
#define IN_DIM 128
#define HID    32
#define OUTD   64
#define F1     256   // H1*HID
#define F2     256   // H2*HID

// ---------------- static scratch (no allocations allowed) ----------------
__device__ float    g_bufA[(size_t)NNODES * 256];
__device__ float    g_bufB[(size_t)NNODES * 256];
__device__ int      g_deg[NNODES];
__device__ int      g_fill[NNODES];
__device__ int      g_rowptr[NNODES + 1];
__device__ int      g_csr[NEDGES];
__device__ unsigned g_gmax[64];

// ---------------- helpers ----------------
__device__ __forceinline__ unsigned enc_f(float f) {
    unsigned u = __float_as_uint(f);
    return (u & 0x80000000u) ? ~u : (u | 0x80000000u);
}

// ---------------- CSR build ----------------
__global__ void init_kernel() {
    int i = blockIdx.x * blockDim.x + threadIdx.x;
    if (i < NNODES) { g_deg[i] = 0; g_fill[i] = 0; }
    if (i < 64) g_gmax[i] = 0u;
}

__global__ void hist_kernel(const int* __restrict__ dst) {
    int e = blockIdx.x * blockDim.x + threadIdx.x;
    if (e < NEDGES) atomicAdd(&g_deg[dst[e]], 1);
}

__global__ void scan_kernel() {
    __shared__ int sums[1024];
    const int t = threadIdx.x;
    const int C = (NNODES + 1023) / 1024;  // 49
    int base = t * C;
    int local = 0;
    for (int i = 0; i < C; i++) {
        int idx = base + i;
        if (idx < NNODES) local += g_deg[idx];
    }
    sums[t] = local;
    __syncthreads();
    // inclusive Hillis-Steele scan
    for (int off = 1; off < 1024; off <<= 1) {
        int v = (t >= off) ? sums[t - off] : 0;
        __syncthreads();
        sums[t] += v;
        __syncthreads();
    }
    int prefix = (t == 0) ? 0 : sums[t - 1];
    for (int i = 0; i < C; i++) {
        int idx = base + i;
        if (idx < NNODES) { g_rowptr[idx] = prefix; prefix += g_deg[idx]; }
    }
    if (t == 1023) g_rowptr[NNODES] = NEDGES;
}

__global__ void scatter_kernel(const int* __restrict__ src, const int* __restrict__ dst) {
    int e = blockIdx.x * blockDim.x + threadIdx.x;
    if (e < NEDGES) {
        int d = dst[e];
        int pos = atomicAdd(&g_fill[d], 1);
        g_csr[g_rowptr[d] + pos] = src[e];
    }
}

// ---------------- GEMM: C[M,Nc] = A[M,K] @ W[K,Nc] + bias ----------------
// BM=128, BN=64, BK=16, 128 threads, 8x8 per thread.
#define BM 128
#define BN 64
#define BK 16

__global__ void __launch_bounds__(128) gemm_bias_kernel(
    const float* __restrict__ A, const float* __restrict__ W,
    const float* __restrict__ bias, float* __restrict__ C,
    int M, int K, int Nc)
{
    __shared__ float As[BK][BM];
    __shared__ float Bs[BK][BN];
    const int t  = threadIdx.x;
    const int tx = t & 7;    // col group 0..7
    const int ty = t >> 3;   // row group 0..15
    const int m0 = blockIdx.y * BM;
    const int n0 = blockIdx.x * BN;

    float acc[8][8];
#pragma unroll
    for (int i = 0; i < 8; i++)
#pragma unroll
        for (int j = 0; j < 8; j++) acc[i][j] = 0.f;

    for (int k0 = 0; k0 < K; k0 += BK) {
        // A tile: 128x16 = 512 float4, 4 per thread (transposed into As[k][m])
#pragma unroll
        for (int j = 0; j < 4; j++) {
            int f   = t + 128 * j;
            int row = f >> 2;
            int c4  = f & 3;
            float4 v = make_float4(0.f, 0.f, 0.f, 0.f);
            int gr = m0 + row;
            if (gr < M)
                v = *(const float4*)(A + (size_t)gr * K + k0 + c4 * 4);
            As[c4 * 4 + 0][row] = v.x;
            As[c4 * 4 + 1][row] = v.y;
            As[c4 * 4 + 2][row] = v.z;
            As[c4 * 4 + 3][row] = v.w;
        }
        // B tile: 16x64 = 256 float4, 2 per thread
#pragma unroll
        for (int j = 0; j < 2; j++) {
            int f   = t + 128 * j;
            int row = f >> 4;
            int c4  = f & 15;
            float4 v = *(const float4*)(W + (size_t)(k0 + row) * Nc + n0 + c4 * 4);
            *(float4*)&Bs[row][c4 * 4] = v;
        }
        __syncthreads();
#pragma unroll
        for (int k = 0; k < BK; k++) {
            float ar[8], br[8];
            *(float4*)&ar[0] = *(const float4*)&As[k][ty * 8];
            *(float4*)&ar[4] = *(const float4*)&As[k][ty * 8 + 4];
            *(float4*)&br[0] = *(const float4*)&Bs[k][tx * 8];
            *(float4*)&br[4] = *(const float4*)&Bs[k][tx * 8 + 4];
#pragma unroll
            for (int i = 0; i < 8; i++)
#pragma unroll
                for (int j = 0; j < 8; j++)
                    acc[i][j] = fmaf(ar[i], br[j], acc[i][j]);
        }
        __syncthreads();
    }

#pragma unroll
    for (int i = 0; i < 8; i++) {
        int gr = m0 + ty * 8 + i;
        if (gr < M) {
#pragma unroll
            for (int j = 0; j < 8; j += 4) {
                int gc = n0 + tx * 8 + j;
                float4 v;
                v.x = acc[i][j + 0] + bias[gc + 0];
                v.y = acc[i][j + 1] + bias[gc + 1];
                v.z = acc[i][j + 2] + bias[gc + 2];
                v.w = acc[i][j + 3] + bias[gc + 3];
                *(float4*)(C + (size_t)gr * Nc + gc) = v;
            }
        }
    }
}

// ---------------- edge aggregation, H=8 D=32 (layers 1,2), one warp/node ----
// reg r = head r, lane = dim. Online softmax over in-edges, ELU epilogue.
__global__ void __launch_bounds__(256) agg_h8_kernel(
    const float* __restrict__ h, const float* __restrict__ attn,
    float* __restrict__ outbuf)
{
    const int warp = (blockIdx.x * blockDim.x + threadIdx.x) >> 5;
    const int lane = threadIdx.x & 31;
    if (warp >= NNODES) return;

    float a[8], hd[8];
    const float* hdrow = h + (size_t)warp * 256;
#pragma unroll
    for (int r = 0; r < 8; r++) {
        a[r]  = attn[r * 32 + lane];
        hd[r] = hdrow[r * 32 + lane];
    }

    float m[8], den[8], acc[8];
#pragma unroll
    for (int r = 0; r < 8; r++) { m[r] = -CUDART_INF_F; den[r] = 0.f; acc[r] = 0.f; }

    const int beg = g_rowptr[warp];
    const int end = g_rowptr[warp + 1];
    for (int i = beg; i < end; i++) {
        int s = g_csr[i];
        const float* hsrow = h + (size_t)s * 256;
        float hs[8], sc[8];
#pragma unroll
        for (int r = 0; r < 8; r++) hs[r] = hsrow[r * 32 + lane];
#pragma unroll
        for (int r = 0; r < 8; r++) {
            float tv = hs[r] + hd[r];
            tv = fmaxf(tv, 0.2f * tv);          // leaky_relu
            sc[r] = tv * a[r];
        }
#pragma unroll
        for (int off = 16; off > 0; off >>= 1) {
#pragma unroll
            for (int r = 0; r < 8; r++)
                sc[r] += __shfl_xor_sync(0xffffffffu, sc[r], off);
        }
#pragma unroll
        for (int r = 0; r < 8; r++) {
            float nm    = fmaxf(m[r], sc[r]);
            float scale = __expf(m[r] - nm);
            float w     = __expf(sc[r] - nm);
            den[r] = den[r] * scale + w;
            acc[r] = fmaf(acc[r], scale, w * hs[r]);
            m[r]   = nm;
        }
    }

    float* orow = outbuf + (size_t)warp * 256;
#pragma unroll
    for (int r = 0; r < 8; r++) {
        float v = acc[r] / den[r];
        v = (v > 0.f) ? v : (__expf(v) - 1.f);   // ELU
        orow[r * 32 + lane] = v;
    }
}

// ---------------- layer 3: H=1 D=64, one warp/node, fused graph max-pool ----
__global__ void __launch_bounds__(256) agg_out_kernel(
    const float* __restrict__ h, const float* __restrict__ attn)
{
    __shared__ unsigned sred[64];
    const int tid = threadIdx.x;
    if (tid < 64) sred[tid] = 0u;
    __syncthreads();

    const int warp = (blockIdx.x * blockDim.x + tid) >> 5;
    const int lane = tid & 31;
    if (warp < NNODES) {
        float a0 = attn[lane], a1 = attn[lane + 32];
        const float* hdrow = h + (size_t)warp * 64;
        float hd0 = hdrow[lane], hd1 = hdrow[lane + 32];
        float m = -CUDART_INF_F, den = 0.f, acc0 = 0.f, acc1 = 0.f;
        const int beg = g_rowptr[warp];
        const int end = g_rowptr[warp + 1];
        for (int i = beg; i < end; i++) {
            int s = g_csr[i];
            const float* hsrow = h + (size_t)s * 64;
            float hs0 = hsrow[lane], hs1 = hsrow[lane + 32];
            float t0 = hs0 + hd0; t0 = fmaxf(t0, 0.2f * t0);
            float t1 = hs1 + hd1; t1 = fmaxf(t1, 0.2f * t1);
            float sc = t0 * a0 + t1 * a1;
#pragma unroll
            for (int off = 16; off > 0; off >>= 1)
                sc += __shfl_xor_sync(0xffffffffu, sc, off);
            float nm    = fmaxf(m, sc);
            float scale = __expf(m - nm);
            float w     = __expf(sc - nm);
            den  = den * scale + w;
            acc0 = fmaf(acc0, scale, w * hs0);
            acc1 = fmaf(acc1, scale, w * hs1);
            m = nm;
        }
        float v0 = acc0 / den;
        float v1 = acc1 / den;
        atomicMax(&sred[lane],      enc_f(v0));
        atomicMax(&sred[lane + 32], enc_f(v1));
    }
    __syncthreads();
    if (tid < 64) atomicMax(&g_gmax[tid], sred[tid]);
}

__global__ void final_kernel(float* __restrict__ out) {
    int i = threadIdx.x;
    unsigned k = g_gmax[i];
    unsigned u = (k & 0x80000000u) ? (k ^ 0x80000000u) : ~k;
    out[i] = __uint_as_float(u);
}

// ---------------- launch ----------------
extern "C" void kernel_launch(void* const* d_in, const int* in_sizes, int n_in,
                              void* d_out, int out_size)
{
    const float* x     = (const float*)d_in[0];
    const int*   src   = (const int*)  d_in[1];
    const int*   dst   = (const int*)  d_in[2];
    const float* W1    = (const float*)d_in[3];
    const float* b1    = (const float*)d_in[4];
    const float* attn1 = (const float*)d_in[5];
    const float* W2    = (const float*)d_in[6];
    const float* b2    = (const float*)d_in[7];
    const float* attn2 = (const float*)d_in[8];
    const float* W3    = (const float*)d_in[9];
    const float* b3    = (const float*)d_in[10];
    const float* attn3 = (const float*)d_in[11];
    float* out = (float*)d_out;

    float *bufA = nullptr, *bufB = nullptr;
    cudaGetSymbolAddress((void**)&bufA, g_bufA);
    cudaGetSymbolAddress((void**)&bufB, g_bufB);

    // CSR build (recomputed every launch; deterministic work)
    init_kernel<<<(NNODES + 255) / 256, 256>>>();
    hist_kernel<<<(NEDGES + 255) / 256, 256>>>(dst);
    scan_kernel<<<1, 1024>>>();
    scatter_kernel<<<(NEDGES + 255) / 256, 256>>>(src, dst);

    const int mtiles = (NNODES + BM - 1) / BM;   // 391
    const int aggblk = (NNODES + 7) / 8;         // 6250 (8 warps/block)

    // layer 1
    gemm_bias_kernel<<<dim3(F1 / BN, mtiles), 128>>>(x, W1, b1, bufA, NNODES, IN_DIM, F1);
    agg_h8_kernel<<<aggblk, 256>>>(bufA, attn1, bufB);
    // layer 2
    gemm_bias_kernel<<<dim3(F2 / BN, mtiles), 128>>>(bufB, W2, b2, bufA, NNODES, F1, F2);
    agg_h8_kernel<<<aggblk, 256>>>(bufA, attn2, bufB);
    // layer 3
    gemm_bias_kernel<<<dim3(OUTD / BN, mtiles), 128>>>(bufB, W3, b3, bufA, NNODES, F2, OUTD);
    agg_out_kernel<<<aggblk, 256>>>(bufA, attn3);

    final_kernel<<<1, 64>>>(out);
}

// round 4
// speedup vs baseline: 1.2319x; 1.2319x over previous
#include <cuda_runtime.h>
#include <cuda_bf16.h>
#include <math_constants.h>

#define NNODES 50000
#define NEDGES 800000
#define IN_DIM 128
#define HID    32
#define OUTD   64
#define F1     256   // H1*HID
#define F2     256   // H2*HID

// ---------------- static scratch (no allocations allowed) ----------------
__device__ float    g_bufA[(size_t)NNODES * 256];
__device__ float    g_bufB[(size_t)NNODES * 256];
__device__ int      g_deg[NNODES];
__device__ int      g_fill[NNODES];
__device__ int      g_rowptr[NNODES + 1];
__device__ int      g_csr[NEDGES];
__device__ unsigned g_gmax[64];

// ---------------- helpers ----------------
__device__ __forceinline__ unsigned enc_f(float f) {
    unsigned u = __float_as_uint(f);
    return (u & 0x80000000u) ? ~u : (u | 0x80000000u);
}

// packed f32x2 FMA: d = a*b + d (element-wise on the two packed floats)
__device__ __forceinline__ void ffma2(unsigned long long& d,
                                      unsigned long long a,
                                      unsigned long long b) {
    asm("fma.rn.f32x2 %0, %1, %2, %0;" : "+l"(d) : "l"(a), "l"(b));
}

// ---------------- CSR build ----------------
__global__ void init_kernel() {
    int i = blockIdx.x * blockDim.x + threadIdx.x;
    if (i < NNODES) { g_deg[i] = 0; g_fill[i] = 0; }
    if (i < 64) g_gmax[i] = 0u;
}

__global__ void hist_kernel(const int* __restrict__ dst) {
    int e = blockIdx.x * blockDim.x + threadIdx.x;
    if (e < NEDGES) atomicAdd(&g_deg[dst[e]], 1);
}

__global__ void scan_kernel() {
    __shared__ int sums[1024];
    const int t = threadIdx.x;
    const int C = (NNODES + 1023) / 1024;  // 49
    int base = t * C;
    int local = 0;
    for (int i = 0; i < C; i++) {
        int idx = base + i;
        if (idx < NNODES) local += g_deg[idx];
    }
    sums[t] = local;
    __syncthreads();
    for (int off = 1; off < 1024; off <<= 1) {
        int v = (t >= off) ? sums[t - off] : 0;
        __syncthreads();
        sums[t] += v;
        __syncthreads();
    }
    int prefix = (t == 0) ? 0 : sums[t - 1];
    for (int i = 0; i < C; i++) {
        int idx = base + i;
        if (idx < NNODES) { g_rowptr[idx] = prefix; prefix += g_deg[idx]; }
    }
    if (t == 1023) g_rowptr[NNODES] = NEDGES;
}

__global__ void scatter_kernel(const int* __restrict__ src, const int* __restrict__ dst) {
    int e = blockIdx.x * blockDim.x + threadIdx.x;
    if (e < NEDGES) {
        int d = dst[e];
        int pos = atomicAdd(&g_fill[d], 1);
        g_csr[g_rowptr[d] + pos] = src[e];
    }
}

// ---------------- GEMM: C[M,Nc] = A[M,K] @ W[K,Nc] + bias -----------------
// BM=128, BN=64, BK=16, 128 threads, 8 rows x 8 cols per thread.
// A tile stored DUPLICATED (float2{v,v}) so the inner loop is pure
// LDS.128 + FFMA2 with no packing MOVs. BMP=BM+2 pad keeps 16B alignment.
#define BM 128
#define BN 64
#define BK 16
#define BMP (BM + 2)

__global__ void __launch_bounds__(128) gemm_bias_kernel(
    const float* __restrict__ A, const float* __restrict__ W,
    const float* __restrict__ bias, float* __restrict__ C,
    int M, int K, int Nc)
{
    __shared__ float2 As2[BK][BMP];  // duplicated A tile
    __shared__ float  Bs[BK][BN];
    const int t  = threadIdx.x;
    const int tx = t & 7;    // col group 0..7
    const int ty = t >> 3;   // row group 0..15
    const int m0 = blockIdx.y * BM;
    const int n0 = blockIdx.x * BN;

    unsigned long long acc2[8][4];   // 8 rows x 4 col-pairs
#pragma unroll
    for (int i = 0; i < 8; i++)
#pragma unroll
        for (int j = 0; j < 4; j++) acc2[i][j] = 0ULL;

    for (int k0 = 0; k0 < K; k0 += BK) {
        // A tile: 128x16 floats = 512 float4, 4 per thread, store duplicated
#pragma unroll
        for (int j = 0; j < 4; j++) {
            int f   = t + 128 * j;
            int row = f >> 2;
            int c4  = f & 3;
            float4 v = make_float4(0.f, 0.f, 0.f, 0.f);
            int gr = m0 + row;
            if (gr < M)
                v = *(const float4*)(A + (size_t)gr * K + k0 + c4 * 4);
            As2[c4 * 4 + 0][row] = make_float2(v.x, v.x);
            As2[c4 * 4 + 1][row] = make_float2(v.y, v.y);
            As2[c4 * 4 + 2][row] = make_float2(v.z, v.z);
            As2[c4 * 4 + 3][row] = make_float2(v.w, v.w);
        }
        // B tile: 16x64 = 256 float4, 2 per thread
#pragma unroll
        for (int j = 0; j < 2; j++) {
            int f   = t + 128 * j;
            int row = f >> 4;
            int c4  = f & 15;
            float4 v = *(const float4*)(W + (size_t)(k0 + row) * Nc + n0 + c4 * 4);
            *(float4*)&Bs[row][c4 * 4] = v;
        }
        __syncthreads();
#pragma unroll
        for (int k = 0; k < BK; k++) {
            unsigned long long a2[8], b2[4];
#pragma unroll
            for (int q = 0; q < 4; q++) {   // 4x LDS.128: pairs (2q, 2q+1)
                ulonglong2 av = *(const ulonglong2*)&As2[k][ty * 8 + 2 * q];
                a2[2 * q]     = av.x;
                a2[2 * q + 1] = av.y;
            }
#pragma unroll
            for (int p = 0; p < 2; p++) {   // 2x LDS.128: col-pairs (2p, 2p+1)
                ulonglong2 bv = *(const ulonglong2*)&Bs[k][tx * 8 + 4 * p];
                b2[2 * p]     = bv.x;
                b2[2 * p + 1] = bv.y;
            }
#pragma unroll
            for (int i = 0; i < 8; i++)
#pragma unroll
                for (int j = 0; j < 4; j++)
                    ffma2(acc2[i][j], a2[i], b2[j]);
        }
        __syncthreads();
    }

#pragma unroll
    for (int i = 0; i < 8; i++) {
        int gr = m0 + ty * 8 + i;
        if (gr < M) {
#pragma unroll
            for (int j = 0; j < 2; j++) {   // two float4 stores
                int gc = n0 + tx * 8 + j * 4;
                float2 p0 = *(float2*)&acc2[i][j * 2 + 0];
                float2 p1 = *(float2*)&acc2[i][j * 2 + 1];
                float4 v;
                v.x = p0.x + bias[gc + 0];
                v.y = p0.y + bias[gc + 1];
                v.z = p1.x + bias[gc + 2];
                v.w = p1.y + bias[gc + 3];
                *(float4*)(C + (size_t)gr * Nc + gc) = v;
            }
        }
    }
}

// ------- 8-head sum reduction: 24 shuffles (fold regs while butterflying) ----
// in: sc[8] per-lane partials. out: sc[r] = sum over all lanes, broadcast.
__device__ __forceinline__ void reduce_heads8(float sc[8], int lane) {
#pragma unroll
    for (int r = 0; r < 8; r++) sc[r] += __shfl_xor_sync(0xffffffffu, sc[r], 16);
    const bool b4 = (lane & 16) != 0;
    float y0 = b4 ? sc[4] : sc[0];
    float y1 = b4 ? sc[5] : sc[1];
    float y2 = b4 ? sc[6] : sc[2];
    float y3 = b4 ? sc[7] : sc[3];
    y0 += __shfl_xor_sync(0xffffffffu, y0, 8);
    y1 += __shfl_xor_sync(0xffffffffu, y1, 8);
    y2 += __shfl_xor_sync(0xffffffffu, y2, 8);
    y3 += __shfl_xor_sync(0xffffffffu, y3, 8);
    const bool b3 = (lane & 8) != 0;
    float z0 = b3 ? y2 : y0;
    float z1 = b3 ? y3 : y1;
    z0 += __shfl_xor_sync(0xffffffffu, z0, 4);
    z1 += __shfl_xor_sync(0xffffffffu, z1, 4);
    float w = (lane & 4) ? z1 : z0;      // lane holds head (lane>>2)&7
    w += __shfl_xor_sync(0xffffffffu, w, 2);
    w += __shfl_xor_sync(0xffffffffu, w, 1);
#pragma unroll
    for (int r = 0; r < 8; r++) sc[r] = __shfl_sync(0xffffffffu, w, r << 2);
}

// online-softmax update with a SINGLE exp (exp(min-max) reused as scale or w)
__device__ __forceinline__ void softmax_update8(
    float m[8], float den[8], float acc[8],
    const float sc[8], const float hs[8])
{
#pragma unroll
    for (int r = 0; r < 8; r++) {
        float s  = sc[r];
        float nm = fmaxf(m[r], s);
        float e  = __expf(fminf(m[r], s) - nm);
        bool  gt = s > m[r];
        float scale = gt ? e : 1.f;
        float w     = gt ? 1.f : e;
        den[r] = fmaf(den[r], scale, w);
        acc[r] = fmaf(acc[r], scale, w * hs[r]);
        m[r] = nm;
    }
}

// ---------------- edge aggregation, H=8 D=32 (layers 1,2), one warp/node ----
__global__ void __launch_bounds__(256) agg_h8_kernel(
    const float* __restrict__ h, const float* __restrict__ attn,
    float* __restrict__ outbuf)
{
    const int warp = (blockIdx.x * blockDim.x + threadIdx.x) >> 5;
    const int lane = threadIdx.x & 31;
    if (warp >= NNODES) return;

    float a[8], hd[8];
    const float* hdrow = h + (size_t)warp * 256;
#pragma unroll
    for (int r = 0; r < 8; r++) {
        a[r]  = attn[r * 32 + lane];
        hd[r] = hdrow[r * 32 + lane];
    }

    float m[8], den[8], acc[8];
#pragma unroll
    for (int r = 0; r < 8; r++) { m[r] = -CUDART_INF_F; den[r] = 0.f; acc[r] = 0.f; }

    const int beg = g_rowptr[warp];
    const int end = g_rowptr[warp + 1];
    int i = beg;

    if ((end - beg) & 1) {   // odd prologue
        int s = g_csr[i++];
        const float* hsrow = h + (size_t)s * 256;
        float hs[8], sc[8];
#pragma unroll
        for (int r = 0; r < 8; r++) hs[r] = hsrow[r * 32 + lane];
#pragma unroll
        for (int r = 0; r < 8; r++) {
            float tv = hs[r] + hd[r];
            tv = fmaxf(tv, 0.2f * tv);
            sc[r] = tv * a[r];
        }
        reduce_heads8(sc, lane);
        softmax_update8(m, den, acc, sc, hs);
    }

    for (; i < end; i += 2) {   // 2 edges per iteration for load/shuffle ILP
        int s0 = g_csr[i];
        int s1 = g_csr[i + 1];
        const float* hr0 = h + (size_t)s0 * 256;
        const float* hr1 = h + (size_t)s1 * 256;
        float hs0[8], hs1[8], sc0[8], sc1[8];
#pragma unroll
        for (int r = 0; r < 8; r++) hs0[r] = hr0[r * 32 + lane];
#pragma unroll
        for (int r = 0; r < 8; r++) hs1[r] = hr1[r * 32 + lane];
#pragma unroll
        for (int r = 0; r < 8; r++) {
            float t0 = hs0[r] + hd[r];
            t0 = fmaxf(t0, 0.2f * t0);
            sc0[r] = t0 * a[r];
            float t1 = hs1[r] + hd[r];
            t1 = fmaxf(t1, 0.2f * t1);
            sc1[r] = t1 * a[r];
        }
        reduce_heads8(sc0, lane);
        reduce_heads8(sc1, lane);
        softmax_update8(m, den, acc, sc0, hs0);
        softmax_update8(m, den, acc, sc1, hs1);
    }

    float* orow = outbuf + (size_t)warp * 256;
#pragma unroll
    for (int r = 0; r < 8; r++) {
        float v = acc[r] / den[r];
        v = (v > 0.f) ? v : (__expf(v) - 1.f);   // ELU
        orow[r * 32 + lane] = v;
    }
}

// ---------------- layer 3: H=1 D=64, one warp/node, fused graph max-pool ----
__global__ void __launch_bounds__(256) agg_out_kernel(
    const float* __restrict__ h, const float* __restrict__ attn)
{
    __shared__ unsigned sred[64];
    const int tid = threadIdx.x;
    if (tid < 64) sred[tid] = 0u;
    __syncthreads();

    const int warp = (blockIdx.x * blockDim.x + tid) >> 5;
    const int lane = tid & 31;
    if (warp < NNODES) {
        float a0 = attn[lane], a1 = attn[lane + 32];
        const float* hdrow = h + (size_t)warp * 64;
        float hd0 = hdrow[lane], hd1 = hdrow[lane + 32];
        float m = -CUDART_INF_F, den = 0.f, acc0 = 0.f, acc1 = 0.f;
        const int beg = g_rowptr[warp];
        const int end = g_rowptr[warp + 1];
        for (int i = beg; i < end; i++) {
            int s = g_csr[i];
            const float* hsrow = h + (size_t)s * 64;
            float hs0 = hsrow[lane], hs1 = hsrow[lane + 32];
            float t0 = hs0 + hd0; t0 = fmaxf(t0, 0.2f * t0);
            float t1 = hs1 + hd1; t1 = fmaxf(t1, 0.2f * t1);
            float sc = fmaf(t0, a0, t1 * a1);
#pragma unroll
            for (int off = 16; off > 0; off >>= 1)
                sc += __shfl_xor_sync(0xffffffffu, sc, off);
            float nm = fmaxf(m, sc);
            float e  = __expf(fminf(m, sc) - nm);
            bool  gt = sc > m;
            float scale = gt ? e : 1.f;
            float w     = gt ? 1.f : e;
            den  = fmaf(den, scale, w);
            acc0 = fmaf(acc0, scale, w * hs0);
            acc1 = fmaf(acc1, scale, w * hs1);
            m = nm;
        }
        float v0 = acc0 / den;
        float v1 = acc1 / den;
        atomicMax(&sred[lane],      enc_f(v0));
        atomicMax(&sred[lane + 32], enc_f(v1));
    }
    __syncthreads();
    if (tid < 64) atomicMax(&g_gmax[tid], sred[tid]);
}

__global__ void final_kernel(float* __restrict__ out) {
    int i = threadIdx.x;
    unsigned k = g_gmax[i];
    unsigned u = (k & 0x80000000u) ? (k ^ 0x80000000u) : ~k;
    out[i] = __uint_as_float(u);
}

// ---------------- launch ----------------
extern "C" void kernel_launch(void* const* d_in, const int* in_sizes, int n_in,
                              void* d_out, int out_size)
{
    const float* x     = (const float*)d_in[0];
    const int*   src   = (const int*)  d_in[1];
    const int*   dst   = (const int*)  d_in[2];
    const float* W1    = (const float*)d_in[3];
    const float* b1    = (const float*)d_in[4];
    const float* attn1 = (const float*)d_in[5];
    const float* W2    = (const float*)d_in[6];
    const float* b2    = (const float*)d_in[7];
    const float* attn2 = (const float*)d_in[8];
    const float* W3    = (const float*)d_in[9];
    const float* b3    = (const float*)d_in[10];
    const float* attn3 = (const float*)d_in[11];
    float* out = (float*)d_out;

    float *bufA = nullptr, *bufB = nullptr;
    cudaGetSymbolAddress((void**)&bufA, g_bufA);
    cudaGetSymbolAddress((void**)&bufB, g_bufB);

    // CSR build (recomputed every launch; deterministic work)
    init_kernel<<<(NNODES + 255) / 256, 256>>>();
    hist_kernel<<<(NEDGES + 255) / 256, 256>>>(dst);
    scan_kernel<<<1, 1024>>>();
    scatter_kernel<<<(NEDGES + 255) / 256, 256>>>(src, dst);

    const int mtiles = (NNODES + BM - 1) / BM;   // 391
    const int aggblk = (NNODES + 7) / 8;         // 6250 (8 warps/block)

    // layer 1
    gemm_bias_kernel<<<dim3(F1 / BN, mtiles), 128>>>(x, W1, b1, bufA, NNODES, IN_DIM, F1);
    agg_h8_kernel<<<aggblk, 256>>>(bufA, attn1, bufB);
    // layer 2
    gemm_bias_kernel<<<dim3(F2 / BN, mtiles), 128>>>(bufB, W2, b2, bufA, NNODES, F1, F2);
    agg_h8_kernel<<<aggblk, 256>>>(bufA, attn2, bufB);
    // layer 3
    gemm_bias_kernel<<<dim3(OUTD / BN, mtiles), 128>>>(bufB, W3, b3, bufA, NNODES, F2, OUTD);
    agg_out_kernel<<<aggblk, 256>>>(bufA, attn3);

    final_kernel<<<1, 64>>>(out);
}

// round 6
// speedup vs baseline: 1.7681x; 1.4353x over previous
#include <cuda_runtime.h>
#include <cuda_bf16.h>
#include <math_constants.h>

#define NNODES 50000
#define NEDGES 800000
#define IN_DIM 128
#define HID    32
#define OUTD   64
#define F1     256   // H1*HID
#define F2     256   // H2*HID

// ---------------- static scratch (no allocations allowed) ----------------
__device__ float    g_bufA[(size_t)NNODES * 256];
__device__ float    g_bufB[(size_t)NNODES * 256];
__device__ int      g_deg[NNODES];
__device__ int      g_fill[NNODES];
__device__ int      g_rowptr[NNODES + 1];
__device__ int      g_csr[NEDGES];
__device__ unsigned g_gmax[64];

// ---------------- helpers ----------------
__device__ __forceinline__ unsigned enc_f(float f) {
    unsigned u = __float_as_uint(f);
    return (u & 0x80000000u) ? ~u : (u | 0x80000000u);
}

// packed f32x2 FMA: d = a*b + d
__device__ __forceinline__ void ffma2(unsigned long long& d,
                                      unsigned long long a,
                                      unsigned long long b) {
    asm("fma.rn.f32x2 %0, %1, %2, %0;" : "+l"(d) : "l"(a), "l"(b));
}

__device__ __forceinline__ float lrelu(float x) { return fmaxf(x, 0.2f * x); }

// ---------------- CSR build ----------------
__global__ void init_kernel() {
    int i = blockIdx.x * blockDim.x + threadIdx.x;
    if (i < NNODES) { g_deg[i] = 0; g_fill[i] = 0; }
    if (i < 64) g_gmax[i] = 0u;
}

__global__ void hist_kernel(const int* __restrict__ dst) {
    int e = blockIdx.x * blockDim.x + threadIdx.x;
    if (e < NEDGES) atomicAdd(&g_deg[dst[e]], 1);
}

__global__ void scan_kernel() {
    __shared__ int sums[1024];
    const int t = threadIdx.x;
    const int C = (NNODES + 1023) / 1024;  // 49
    int base = t * C;
    int local = 0;
    for (int i = 0; i < C; i++) {
        int idx = base + i;
        if (idx < NNODES) local += g_deg[idx];
    }
    sums[t] = local;
    __syncthreads();
    for (int off = 1; off < 1024; off <<= 1) {
        int v = (t >= off) ? sums[t - off] : 0;
        __syncthreads();
        sums[t] += v;
        __syncthreads();
    }
    int prefix = (t == 0) ? 0 : sums[t - 1];
    for (int i = 0; i < C; i++) {
        int idx = base + i;
        if (idx < NNODES) { g_rowptr[idx] = prefix; prefix += g_deg[idx]; }
    }
    if (t == 1023) g_rowptr[NNODES] = NEDGES;
}

__global__ void scatter_kernel(const int* __restrict__ src, const int* __restrict__ dst) {
    int e = blockIdx.x * blockDim.x + threadIdx.x;
    if (e < NEDGES) {
        int d = dst[e];
        int pos = atomicAdd(&g_fill[d], 1);
        g_csr[g_rowptr[d] + pos] = src[e];
    }
}

// ---------------- GEMM: C[M,Nc] = A[M,K] @ W[K,Nc] + bias -----------------
// BM=128, BN=64, BK=16, 128 threads, 8x8 per thread, FFMA2 inner loop,
// double-buffered smem with register staging (1 sync per k-tile).
#define BM 128
#define BN 64
#define BK 16
#define BMP (BM + 2)

__global__ void __launch_bounds__(128) gemm_bias_kernel(
    const float* __restrict__ A, const float* __restrict__ W,
    const float* __restrict__ bias, float* __restrict__ C,
    int M, int K, int Nc)
{
    __shared__ float2 As2[2][BK][BMP];  // duplicated A tile {v,v}
    __shared__ float  Bs[2][BK][BN];
    const int t  = threadIdx.x;
    const int tx = t & 7;
    const int ty = t >> 3;
    const int m0 = blockIdx.y * BM;
    const int n0 = blockIdx.x * BN;

    // loader coordinates (fixed per thread)
    const int arow0 = t >> 2;          // + 32*j
    const int ac4   = t & 3;
    const int brow0 = t >> 4;          // + 8*j
    const int bc4   = t & 15;

    unsigned long long acc2[8][4];
#pragma unroll
    for (int i = 0; i < 8; i++)
#pragma unroll
        for (int j = 0; j < 4; j++) acc2[i][j] = 0ULL;

    float4 va[4], vb[2];

    auto load_regs = [&](int k0) {
#pragma unroll
        for (int j = 0; j < 4; j++) {
            int row = arow0 + 32 * j;
            int gr  = m0 + row;
            va[j] = make_float4(0.f, 0.f, 0.f, 0.f);
            if (gr < M)
                va[j] = *(const float4*)(A + (size_t)gr * K + k0 + ac4 * 4);
        }
#pragma unroll
        for (int j = 0; j < 2; j++) {
            int row = brow0 + 8 * j;
            vb[j] = *(const float4*)(W + (size_t)(k0 + row) * Nc + n0 + bc4 * 4);
        }
    };
    auto store_smem = [&](int buf) {
#pragma unroll
        for (int j = 0; j < 4; j++) {
            int row = arow0 + 32 * j;
            As2[buf][ac4 * 4 + 0][row] = make_float2(va[j].x, va[j].x);
            As2[buf][ac4 * 4 + 1][row] = make_float2(va[j].y, va[j].y);
            As2[buf][ac4 * 4 + 2][row] = make_float2(va[j].z, va[j].z);
            As2[buf][ac4 * 4 + 3][row] = make_float2(va[j].w, va[j].w);
        }
#pragma unroll
        for (int j = 0; j < 2; j++) {
            int row = brow0 + 8 * j;
            *(float4*)&Bs[buf][row][bc4 * 4] = vb[j];
        }
    };

    const int ntiles = K / BK;
    load_regs(0);
    store_smem(0);
    __syncthreads();

    for (int tt = 0; tt < ntiles; tt++) {
        const int buf = tt & 1;
        if (tt + 1 < ntiles) load_regs((tt + 1) * BK);
#pragma unroll
        for (int k = 0; k < BK; k++) {
            unsigned long long a2[8], b2[4];
#pragma unroll
            for (int q = 0; q < 4; q++) {
                ulonglong2 av = *(const ulonglong2*)&As2[buf][k][ty * 8 + 2 * q];
                a2[2 * q]     = av.x;
                a2[2 * q + 1] = av.y;
            }
#pragma unroll
            for (int p = 0; p < 2; p++) {
                ulonglong2 bv = *(const ulonglong2*)&Bs[buf][k][tx * 8 + 4 * p];
                b2[2 * p]     = bv.x;
                b2[2 * p + 1] = bv.y;
            }
#pragma unroll
            for (int i = 0; i < 8; i++)
#pragma unroll
                for (int j = 0; j < 4; j++)
                    ffma2(acc2[i][j], a2[i], b2[j]);
        }
        if (tt + 1 < ntiles) store_smem(buf ^ 1);
        __syncthreads();
    }

#pragma unroll
    for (int i = 0; i < 8; i++) {
        int gr = m0 + ty * 8 + i;
        if (gr < M) {
#pragma unroll
            for (int j = 0; j < 2; j++) {
                int gc = n0 + tx * 8 + j * 4;
                float2 p0 = *(float2*)&acc2[i][j * 2 + 0];
                float2 p1 = *(float2*)&acc2[i][j * 2 + 1];
                float4 v;
                v.x = p0.x + bias[gc + 0];
                v.y = p0.y + bias[gc + 1];
                v.z = p1.x + bias[gc + 2];
                v.w = p1.y + bias[gc + 3];
                *(float4*)(C + (size_t)gr * Nc + gc) = v;
            }
        }
    }
}

// --------- online-softmax update for one head slot (float4 payload) --------
__device__ __forceinline__ void upd4(float& m, float& den, float4& acc,
                                     float p, const float4& s)
{
    float nm = fmaxf(m, p);
    float e  = __expf(fminf(m, p) - nm);
    bool  gt = p > m;
    float scale = gt ? e : 1.f;
    float w     = gt ? 1.f : e;
    den   = fmaf(den, scale, w);
    acc.x = fmaf(acc.x, scale, w * s.x);
    acc.y = fmaf(acc.y, scale, w * s.y);
    acc.z = fmaf(acc.z, scale, w * s.z);
    acc.w = fmaf(acc.w, scale, w * s.w);
    m = nm;
}

// leaky-relu(s+d) . a   (4-wide partial)
__device__ __forceinline__ float dp_lr4(const float4& s, const float4& d,
                                        const float4& a)
{
    float p;
    p = lrelu(s.x + d.x) * a.x;
    p = fmaf(lrelu(s.y + d.y), a.y, p);
    p = fmaf(lrelu(s.z + d.z), a.z, p);
    p = fmaf(lrelu(s.w + d.w), a.w, p);
    return p;
}

// ---------------- edge aggregation, H=8 D=32 (layers 1,2) ------------------
// Packed layout: lane l holds floats [4l..4l+3] (head l>>3, vec0) and
// [128+4l..128+4l+3] (head 4+(l>>3), vec1). Segmented 8-lane reductions;
// no broadcast shuffles; 2 exp per edge.
__global__ void __launch_bounds__(256) agg_h8_kernel(
    const float* __restrict__ h, const float* __restrict__ attn,
    float* __restrict__ outbuf)
{
    const int warp = (blockIdx.x * blockDim.x + threadIdx.x) >> 5;
    const int lane = threadIdx.x & 31;
    if (warp >= NNODES) return;

    const float4* arow = (const float4*)attn;
    const float4  a0 = arow[lane];
    const float4  a1 = arow[lane + 32];
    const float4* drow = (const float4*)(h + (size_t)warp * 256);
    const float4  d0 = drow[lane];
    const float4  d1 = drow[lane + 32];

    float  m0 = -CUDART_INF_F, m1 = -CUDART_INF_F;
    float  den0 = 0.f, den1 = 0.f;
    float4 acc0 = make_float4(0.f, 0.f, 0.f, 0.f);
    float4 acc1 = make_float4(0.f, 0.f, 0.f, 0.f);

    const int beg = g_rowptr[warp];
    const int end = g_rowptr[warp + 1];
    int i = beg;

    if ((end - beg) & 1) {
        int s = g_csr[i++];
        const float4* srow = (const float4*)(h + (size_t)s * 256);
        float4 s0 = srow[lane], s1 = srow[lane + 32];
        float p0 = dp_lr4(s0, d0, a0);
        float p1 = dp_lr4(s1, d1, a1);
        p0 += __shfl_xor_sync(0xffffffffu, p0, 1);
        p1 += __shfl_xor_sync(0xffffffffu, p1, 1);
        p0 += __shfl_xor_sync(0xffffffffu, p0, 2);
        p1 += __shfl_xor_sync(0xffffffffu, p1, 2);
        p0 += __shfl_xor_sync(0xffffffffu, p0, 4);
        p1 += __shfl_xor_sync(0xffffffffu, p1, 4);
        upd4(m0, den0, acc0, p0, s0);
        upd4(m1, den1, acc1, p1, s1);
    }

    for (; i < end; i += 2) {
        int sA = g_csr[i];
        int sB = g_csr[i + 1];
        const float4* rA = (const float4*)(h + (size_t)sA * 256);
        const float4* rB = (const float4*)(h + (size_t)sB * 256);
        float4 sA0 = rA[lane], sA1 = rA[lane + 32];
        float4 sB0 = rB[lane], sB1 = rB[lane + 32];
        float pA0 = dp_lr4(sA0, d0, a0);
        float pA1 = dp_lr4(sA1, d1, a1);
        float pB0 = dp_lr4(sB0, d0, a0);
        float pB1 = dp_lr4(sB1, d1, a1);
#pragma unroll
        for (int off = 1; off <= 4; off <<= 1) {
            pA0 += __shfl_xor_sync(0xffffffffu, pA0, off);
            pA1 += __shfl_xor_sync(0xffffffffu, pA1, off);
            pB0 += __shfl_xor_sync(0xffffffffu, pB0, off);
            pB1 += __shfl_xor_sync(0xffffffffu, pB1, off);
        }
        upd4(m0, den0, acc0, pA0, sA0);
        upd4(m1, den1, acc1, pA1, sA1);
        upd4(m0, den0, acc0, pB0, sB0);
        upd4(m1, den1, acc1, pB1, sB1);
    }

    const float inv0 = 1.f / den0;
    const float inv1 = 1.f / den1;
    float4 v0, v1;
    v0.x = acc0.x * inv0; v0.y = acc0.y * inv0;
    v0.z = acc0.z * inv0; v0.w = acc0.w * inv0;
    v1.x = acc1.x * inv1; v1.y = acc1.y * inv1;
    v1.z = acc1.z * inv1; v1.w = acc1.w * inv1;
    // ELU
    v0.x = (v0.x > 0.f) ? v0.x : (__expf(v0.x) - 1.f);
    v0.y = (v0.y > 0.f) ? v0.y : (__expf(v0.y) - 1.f);
    v0.z = (v0.z > 0.f) ? v0.z : (__expf(v0.z) - 1.f);
    v0.w = (v0.w > 0.f) ? v0.w : (__expf(v0.w) - 1.f);
    v1.x = (v1.x > 0.f) ? v1.x : (__expf(v1.x) - 1.f);
    v1.y = (v1.y > 0.f) ? v1.y : (__expf(v1.y) - 1.f);
    v1.z = (v1.z > 0.f) ? v1.z : (__expf(v1.z) - 1.f);
    v1.w = (v1.w > 0.f) ? v1.w : (__expf(v1.w) - 1.f);

    float4* orow = (float4*)(outbuf + (size_t)warp * 256);
    orow[lane]      = v0;
    orow[lane + 32] = v1;
}

// ---------------- layer 3: H=1 D=64, packed float2, fused max-pool ---------
__global__ void __launch_bounds__(256) agg_out_kernel(
    const float* __restrict__ h, const float* __restrict__ attn)
{
    __shared__ unsigned sred[64];
    const int tid = threadIdx.x;
    if (tid < 64) sred[tid] = 0u;
    __syncthreads();

    const int warp = (blockIdx.x * blockDim.x + tid) >> 5;
    const int lane = tid & 31;
    if (warp < NNODES) {
        const float2 a = ((const float2*)attn)[lane];
        const float2 d = ((const float2*)(h + (size_t)warp * 64))[lane];
        float m = -CUDART_INF_F, den = 0.f;
        float2 acc = make_float2(0.f, 0.f);
        const int beg = g_rowptr[warp];
        const int end = g_rowptr[warp + 1];
        for (int i = beg; i < end; i++) {
            int s = g_csr[i];
            const float2 sv = ((const float2*)(h + (size_t)s * 64))[lane];
            float p = lrelu(sv.x + d.x) * a.x;
            p = fmaf(lrelu(sv.y + d.y), a.y, p);
#pragma unroll
            for (int off = 16; off > 0; off >>= 1)
                p += __shfl_xor_sync(0xffffffffu, p, off);
            float nm = fmaxf(m, p);
            float e  = __expf(fminf(m, p) - nm);
            bool  gt = p > m;
            float scale = gt ? e : 1.f;
            float w     = gt ? 1.f : e;
            den   = fmaf(den, scale, w);
            acc.x = fmaf(acc.x, scale, w * sv.x);
            acc.y = fmaf(acc.y, scale, w * sv.y);
            m = nm;
        }
        float inv = 1.f / den;
        atomicMax(&sred[2 * lane],     enc_f(acc.x * inv));
        atomicMax(&sred[2 * lane + 1], enc_f(acc.y * inv));
    }
    __syncthreads();
    if (tid < 64) atomicMax(&g_gmax[tid], sred[tid]);
}

__global__ void final_kernel(float* __restrict__ out) {
    int i = threadIdx.x;
    unsigned k = g_gmax[i];
    unsigned u = (k & 0x80000000u) ? (k ^ 0x80000000u) : ~k;
    out[i] = __uint_as_float(u);
}

// ---------------- launch ----------------
extern "C" void kernel_launch(void* const* d_in, const int* in_sizes, int n_in,
                              void* d_out, int out_size)
{
    const float* x     = (const float*)d_in[0];
    const int*   src   = (const int*)  d_in[1];
    const int*   dst   = (const int*)  d_in[2];
    const float* W1    = (const float*)d_in[3];
    const float* b1    = (const float*)d_in[4];
    const float* attn1 = (const float*)d_in[5];
    const float* W2    = (const float*)d_in[6];
    const float* b2    = (const float*)d_in[7];
    const float* attn2 = (const float*)d_in[8];
    const float* W3    = (const float*)d_in[9];
    const float* b3    = (const float*)d_in[10];
    const float* attn3 = (const float*)d_in[11];
    float* out = (float*)d_out;

    float *bufA = nullptr, *bufB = nullptr;
    cudaGetSymbolAddress((void**)&bufA, g_bufA);
    cudaGetSymbolAddress((void**)&bufB, g_bufB);

    // CSR build
    init_kernel<<<(NNODES + 255) / 256, 256>>>();
    hist_kernel<<<(NEDGES + 255) / 256, 256>>>(dst);
    scan_kernel<<<1, 1024>>>();
    scatter_kernel<<<(NEDGES + 255) / 256, 256>>>(src, dst);

    const int mtiles = (NNODES + BM - 1) / BM;   // 391
    const int aggblk = (NNODES + 7) / 8;         // 6250

    // layer 1
    gemm_bias_kernel<<<dim3(F1 / BN, mtiles), 128>>>(x, W1, b1, bufA, NNODES, IN_DIM, F1);
    agg_h8_kernel<<<aggblk, 256>>>(bufA, attn1, bufB);
    // layer 2
    gemm_bias_kernel<<<dim3(F2 / BN, mtiles), 128>>>(bufB, W2, b2, bufA, NNODES, F1, F2);
    agg_h8_kernel<<<aggblk, 256>>>(bufA, attn2, bufB);
    // layer 3
    gemm_bias_kernel<<<dim3(OUTD / BN, mtiles), 128>>>(bufB, W3, b3, bufA, NNODES, F2, OUTD);
    agg_out_kernel<<<aggblk, 256>>>(bufA, attn3);

    final_kernel<<<1, 64>>>(out);
}